// round 3
// baseline (speedup 1.0000x reference)
#include <cuda_runtime.h>
#include <cstdint>

typedef unsigned long long u64;

#define TT 512
#define BB 64
#define DD 512
#define HH 512
#define G4 2048
#define NCTA 128

// ---------------------------------------------------------------------------
// Device-global scratch (allowed; no dynamic allocation)
// ---------------------------------------------------------------------------
__device__ float g_G[(size_t)2 * TT * G4 * BB];   // 512 MB: precomputed x@Wih^T + bias
__device__ float g_h[2][2][HH][BB];               // [buf][dir][k][b]
__device__ unsigned g_bar_count;
__device__ volatile unsigned g_bar_gen;

// ---------------------------------------------------------------------------
// f32x2 packed helpers (sm_103a FFMA2: double-rate fp32)
// ---------------------------------------------------------------------------
__device__ __forceinline__ u64 pk2(float a, float b) {
    u64 r; asm("mov.b64 %0, {%1,%2};" : "=l"(r) : "f"(a), "f"(b)); return r;
}
__device__ __forceinline__ void fma2(u64& d, u64 a, u64 b) {
    asm("fma.rn.f32x2 %0, %1, %2, %0;" : "+l"(d) : "l"(a), "l"(b));
}
__device__ __forceinline__ float2 unpk(u64 v) {
    float2 r; asm("mov.b64 {%0,%1}, %2;" : "=f"(r.x), "=f"(r.y) : "l"(v)); return r;
}
__device__ __forceinline__ float sigf(float x) { return 1.0f / (1.0f + __expf(-x)); }

__device__ __forceinline__ unsigned smem_u32(const void* p) {
    return (unsigned)__cvta_generic_to_shared(p);
}
__device__ __forceinline__ void cp16(unsigned dst, const void* src) {
    asm volatile("cp.async.cg.shared.global [%0], [%1], 16;" :: "r"(dst), "l"(src) : "memory");
}
__device__ __forceinline__ void cp_commit() {
    asm volatile("cp.async.commit_group;" ::: "memory");
}

// ---------------------------------------------------------------------------
// Grid barrier: all NCTA CTAs resident (128 <= 148 SMs, 1 CTA/SM)
// ---------------------------------------------------------------------------
__device__ __forceinline__ void grid_barrier() {
    __threadfence();
    __syncthreads();
    if (threadIdx.x == 0) {
        unsigned gen = g_bar_gen;
        __threadfence();
        if (atomicAdd(&g_bar_count, 1u) == NCTA - 1) {
            g_bar_count = 0;
            __threadfence();
            g_bar_gen = gen + 1;
        } else {
            while (g_bar_gen == gen) { }
        }
        __threadfence();
    }
    __syncthreads();
}

// ---------------------------------------------------------------------------
// Phase 1: G[dir][s][n][b] = bias[n] + sum_d W[n][d] * x[t][b][d]
// CTA tile 128n x 64b, K-chunks of 32. Thread tile 8n x 4b (f32x2 over b).
// ---------------------------------------------------------------------------
__global__ void __launch_bounds__(256) phase1_kernel(
    const float* __restrict__ x,
    const float* __restrict__ Wf, const float* __restrict__ Wr,
    const float* __restrict__ bif, const float* __restrict__ bhf,
    const float* __restrict__ bir, const float* __restrict__ bhr)
{
    __shared__ __align__(16) float Wt[32][132];
    __shared__ __align__(16) float Xt[32][68];

    const int tid = threadIdx.x;
    const int n0  = blockIdx.x * 128;
    const int s   = blockIdx.y;
    const int dir = blockIdx.z;
    const int tt  = dir ? (TT - 1 - s) : s;
    const float* __restrict__ W = dir ? Wr : Wf;

    const int bg = tid & 15;   // b quad: 4*bg .. 4*bg+3
    const int ng = tid >> 4;   // n group: 8*ng .. 8*ng+7

    u64 acc[8][2];
#pragma unroll
    for (int i = 0; i < 8; i++) { acc[i][0] = 0ull; acc[i][1] = 0ull; }

    const float* xbase = x + (size_t)tt * BB * DD;

    for (int d0 = 0; d0 < DD; d0 += 32) {
        __syncthreads();
        // W tile -> Wt[k][n]
#pragma unroll
        for (int i = 0; i < 4; i++) {
            int lin = tid + 256 * i;           // 0..1023
            int n = lin >> 3, kq = lin & 7;
            float4 w = *(const float4*)(W + (size_t)(n0 + n) * DD + d0 + kq * 4);
            Wt[kq*4+0][n] = w.x; Wt[kq*4+1][n] = w.y;
            Wt[kq*4+2][n] = w.z; Wt[kq*4+3][n] = w.w;
        }
        // X tile -> Xt[k][b]
#pragma unroll
        for (int i = 0; i < 2; i++) {
            int lin = tid + 256 * i;           // 0..511
            int b = lin >> 3, kq = lin & 7;
            float4 v = *(const float4*)(xbase + (size_t)b * DD + d0 + kq * 4);
            Xt[kq*4+0][b] = v.x; Xt[kq*4+1][b] = v.y;
            Xt[kq*4+2][b] = v.z; Xt[kq*4+3][b] = v.w;
        }
        __syncthreads();
#pragma unroll 8
        for (int k = 0; k < 32; k++) {
            float4 xa = *(const float4*)&Xt[k][bg * 4];
            u64 xv0 = pk2(xa.x, xa.y);
            u64 xv1 = pk2(xa.z, xa.w);
            float wv[8];
            *(float4*)&wv[0] = *(const float4*)&Wt[k][ng * 8];
            *(float4*)&wv[4] = *(const float4*)&Wt[k][ng * 8 + 4];
#pragma unroll
            for (int i = 0; i < 8; i++) {
                u64 w = pk2(wv[i], wv[i]);
                fma2(acc[i][0], w, xv0);
                fma2(acc[i][1], w, xv1);
            }
        }
    }

    const float* bi = dir ? bir : bif;
    const float* bh = dir ? bhr : bhf;
    float* Gp = g_G + ((size_t)(dir * TT + s) * G4 + n0 + ng * 8) * BB;
#pragma unroll
    for (int i = 0; i < 8; i++) {
        int n = n0 + ng * 8 + i;
        float bsum = bi[n] + bh[n];
        float2 p0 = unpk(acc[i][0]);
        float2 p1 = unpk(acc[i][1]);
        float4 o = make_float4(p0.x + bsum, p0.y + bsum, p1.x + bsum, p1.y + bsum);
        *(float4*)(Gp + (size_t)i * BB + bg * 4) = o;
    }
}

// ---------------------------------------------------------------------------
// Phase 2: persistent recurrence. 128 CTAs x 128 threads.
// CTA (dir, j0): 8 hidden units, 32 gate rows. Whh rows resident in SMEM
// transposed Ws[k][rr] (rr = gate*8+u). Thread: rows 2rp,2rp+1; b = 8*bo..+7.
// ---------------------------------------------------------------------------
__global__ void __launch_bounds__(128) phase2_kernel(
    const float* __restrict__ Whf, const float* __restrict__ Whr,
    const float* __restrict__ mask, float* __restrict__ out)
{
    extern __shared__ float sm[];
    float* Ws   = sm;                 // [512][32]      64 KB
    float* hsm  = Ws + 512 * 32;      // [2][64][64]    32 KB
    float* gbuf = hsm + 2 * 64 * 64;  // [32][64]        8 KB
    float* csm  = gbuf + 32 * 64;     // [8][64]         2 KB
    float* hosm = csm + 8 * 64;       // [8][64]         2 KB

    const int tid = threadIdx.x;
    const int cid = blockIdx.x;
    const int dir = cid >> 6;
    const int j0  = (cid & 63) * 8;
    const float* __restrict__ Whh = dir ? Whr : Whf;

    // Load Whh rows transposed into Ws[k][rr]
    for (int i = tid; i < 32 * 128; i += 128) {
        int rr = i >> 7, kq = i & 127;
        int gate = rr >> 3, u = rr & 7;
        float4 w = *(const float4*)(Whh + (size_t)(gate * HH + j0 + u) * HH + kq * 4);
        Ws[(kq*4+0)*32 + rr] = w.x; Ws[(kq*4+1)*32 + rr] = w.y;
        Ws[(kq*4+2)*32 + rr] = w.z; Ws[(kq*4+3)*32 + rr] = w.w;
    }
    // Zero state (determinism across graph replays)
    for (int i = tid; i < 8 * 64; i += 128) {
        csm[i] = 0.0f; hosm[i] = 0.0f;
        g_h[0][dir][j0 + (i >> 6)][i & 63] = 0.0f;
    }
    grid_barrier();

    const int rp = tid >> 3, bo = tid & 7;
    const int r0 = 2 * rp, r1 = r0 + 1;
    const int gate = r0 >> 3;
    const int u0 = r0 & 7;

    // Prefetch h chunk 0 of step 0
    {
        const char* src = (const char*)&g_h[0][dir][0][0];
        unsigned dst = smem_u32(hsm);
#pragma unroll
        for (int i = 0; i < 8; i++)
            cp16(dst + tid * 16 + i * 2048, src + tid * 16 + i * 2048);
        cp_commit();
    }

    for (int s = 0; s < TT; s++) {
        const int pb = s & 1, nb = pb ^ 1;
        const int tg = dir ? (TT - 1 - s) : s;

        // acc initialized from precomputed G (input contribution + bias)
        u64 a0[4], a1[4];
        {
            const float* Gp = g_G + ((size_t)(dir * TT + s) * G4 + gate * HH + j0 + u0) * BB + bo * 8;
            ulonglong2 q0 = *(const ulonglong2*)Gp;
            ulonglong2 q1 = *(const ulonglong2*)(Gp + 4);
            ulonglong2 q2 = *(const ulonglong2*)(Gp + BB);
            ulonglong2 q3 = *(const ulonglong2*)(Gp + BB + 4);
            a0[0] = q0.x; a0[1] = q0.y; a0[2] = q1.x; a0[3] = q1.y;
            a1[0] = q2.x; a1[1] = q2.y; a1[2] = q3.x; a1[3] = q3.y;
        }

        // k-loop: 8 chunks of 64, cp.async double-buffered
        for (int ch = 0; ch < 8; ch++) {
            if (ch < 7) {
                const char* src = (const char*)&g_h[pb][dir][(ch + 1) * 64][0];
                unsigned dst = smem_u32(hsm + ((ch + 1) & 1) * 4096);
#pragma unroll
                for (int i = 0; i < 8; i++)
                    cp16(dst + tid * 16 + i * 2048, src + tid * 16 + i * 2048);
                cp_commit();
                asm volatile("cp.async.wait_group 1;" ::: "memory");
            } else {
                asm volatile("cp.async.wait_group 0;" ::: "memory");
            }
            __syncthreads();
            const float* hb = hsm + (ch & 1) * 4096 + bo * 8;
            const float* wp = Ws + (ch * 64) * 32 + r0;
#pragma unroll 4
            for (int kk = 0; kk < 64; kk++) {
                float2 w2 = *(const float2*)(wp + kk * 32);
                u64 w0 = pk2(w2.x, w2.x);
                u64 w1 = pk2(w2.y, w2.y);
                ulonglong2 h01 = *(const ulonglong2*)(hb + kk * 64);
                ulonglong2 h23 = *(const ulonglong2*)(hb + kk * 64 + 4);
                fma2(a0[0], w0, h01.x); fma2(a0[1], w0, h01.y);
                fma2(a0[2], w0, h23.x); fma2(a0[3], w0, h23.y);
                fma2(a1[0], w1, h01.x); fma2(a1[1], w1, h01.y);
                fma2(a1[2], w1, h23.x); fma2(a1[3], w1, h23.y);
            }
            __syncthreads();
        }

        // Gate values -> gbuf
        {
            float2 p; float4 v;
            p = unpk(a0[0]); v.x = p.x; v.y = p.y;
            p = unpk(a0[1]); v.z = p.x; v.w = p.y;
            *(float4*)&gbuf[r0 * 64 + bo * 8] = v;
            p = unpk(a0[2]); v.x = p.x; v.y = p.y;
            p = unpk(a0[3]); v.z = p.x; v.w = p.y;
            *(float4*)&gbuf[r0 * 64 + bo * 8 + 4] = v;
            p = unpk(a1[0]); v.x = p.x; v.y = p.y;
            p = unpk(a1[1]); v.z = p.x; v.w = p.y;
            *(float4*)&gbuf[r1 * 64 + bo * 8] = v;
            p = unpk(a1[2]); v.x = p.x; v.y = p.y;
            p = unpk(a1[3]); v.z = p.x; v.w = p.y;
            *(float4*)&gbuf[r1 * 64 + bo * 8 + 4] = v;
        }
        __syncthreads();

        // Combine gates, update c/h, apply mask, write h + output
#pragma unroll
        for (int i = 0; i < 4; i++) {
            int idx = tid + 128 * i;          // 0..511
            int u = idx >> 6, b = idx & 63;
            float ig = sigf(gbuf[(0  + u) * 64 + b]);
            float fg = sigf(gbuf[(8  + u) * 64 + b]);
            float gg = tanhf(gbuf[(16 + u) * 64 + b]);
            float og = sigf(gbuf[(24 + u) * 64 + b]);
            float c_old = csm[u * 64 + b];
            float c2 = fg * c_old + ig * gg;
            float h2 = og * tanhf(c2);
            float m = mask[(size_t)tg * BB + b];
            float c_new = c_old + m * (c2 - c_old);
            float h_old = hosm[u * 64 + b];
            float h_new = h_old + m * (h2 - h_old);
            csm[u * 64 + b]  = c_new;
            hosm[u * 64 + b] = h_new;
            g_h[nb][dir][j0 + u][b] = h_new;
            out[(size_t)tg * BB * 1024 + (size_t)b * 1024 + dir * HH + j0 + u] = h_new;
        }

        grid_barrier();

        if (s + 1 < TT) {
            const char* src = (const char*)&g_h[nb][dir][0][0];
            unsigned dst = smem_u32(hsm);
#pragma unroll
            for (int i = 0; i < 8; i++)
                cp16(dst + tid * 16 + i * 2048, src + tid * 16 + i * 2048);
            cp_commit();
        }
    }
}

// ---------------------------------------------------------------------------
// Launch
// ---------------------------------------------------------------------------
extern "C" void kernel_launch(void* const* d_in, const int* in_sizes, int n_in,
                              void* d_out, int out_size) {
    const float* x_data = (const float*)d_in[0];
    const float* x_mask = (const float*)d_in[1];
    const float* Wih_f  = (const float*)d_in[2];
    const float* Whh_f  = (const float*)d_in[3];
    const float* bih_f  = (const float*)d_in[4];
    const float* bhh_f  = (const float*)d_in[5];
    const float* Wih_r  = (const float*)d_in[6];
    const float* Whh_r  = (const float*)d_in[7];
    const float* bih_r  = (const float*)d_in[8];
    const float* bhh_r  = (const float*)d_in[9];
    float* out = (float*)d_out;

    static bool attr_set = false;
    if (!attr_set) {
        cudaFuncSetAttribute(phase2_kernel,
                             cudaFuncAttributeMaxDynamicSharedMemorySize, 110592);
        attr_set = true;
    }

    dim3 g1(16, 512, 2);
    phase1_kernel<<<g1, 256>>>(x_data, Wih_f, Wih_r, bih_f, bhh_f, bih_r, bhh_r);
    phase2_kernel<<<NCTA, 128, 110592>>>(Whh_f, Whh_r, x_mask, out);
}